// round 10
// baseline (speedup 1.0000x reference)
#include <cuda_runtime.h>
#include <cuda_fp16.h>
#include <stdint.h>

#define IN_CH   128
#define OUT_CH  64
#define N_MAX   100000
#define E_MAX   1600000
#define SCAN_B  1024
#define NBLK    ((N_MAX + SCAN_B - 1) / SCAN_B)   // 98

// Scratch (device globals — no runtime allocation allowed)
__device__ __half2 g_hh[(size_t)N_MAX * (OUT_CH / 2)];  // 12.8 MB: h in fp16
__device__ float g_dinv[N_MAX];
__device__ int   g_deg[N_MAX];                  // in-edge count (EXCL self loop)
__device__ int   g_off[N_MAX];                  // CSR offsets
__device__ int   g_cur[N_MAX];                  // fill cursors; == end after fill
__device__ int   g_bsum[NBLK];                  // per-block raw sums for scan
__device__ int2  g_csr[E_MAX];                  // (src, bitcast norm) per edge

// ---------------------------------------------------------------------------
// Degree count (vectorized int4 reads; deg starts at 0 via memsetAsync)
// ---------------------------------------------------------------------------
__global__ void deg_count_kernel(const int* __restrict__ dst, int e) {
    int i = blockIdx.x * blockDim.x + threadIdx.x;
    int base = i * 4;
    if (base + 3 < e) {
        int4 d = *(const int4*)(dst + base);
        atomicAdd(&g_deg[d.x], 1);
        atomicAdd(&g_deg[d.y], 1);
        atomicAdd(&g_deg[d.z], 1);
        atomicAdd(&g_deg[d.w], 1);
    } else {
        for (int k = base; k < e; k++) atomicAdd(&g_deg[dst[k]], 1);
    }
}

// ---------------------------------------------------------------------------
// Scan stage 1: block-local exclusive scan of deg; raw block sums out.
// dinv fused in.
// ---------------------------------------------------------------------------
__global__ __launch_bounds__(SCAN_B)
void scan_block_kernel(int n) {
    __shared__ int s[SCAN_B];
    int tid = threadIdx.x;
    int i = blockIdx.x * SCAN_B + tid;
    int c = (i < n) ? g_deg[i] : 0;
    if (i < n) g_dinv[i] = rsqrtf((float)(c + 1));
    s[tid] = c;
    __syncthreads();
#pragma unroll
    for (int off = 1; off < SCAN_B; off <<= 1) {
        int v = (tid >= off) ? s[tid - off] : 0;
        __syncthreads();
        s[tid] += v;
        __syncthreads();
    }
    if (i < n) g_off[i] = s[tid] - c;   // exclusive within block
    if (tid == SCAN_B - 1) g_bsum[blockIdx.x] = s[tid];
}

// ---------------------------------------------------------------------------
// Scan stage 2: each block inlines the prefix over raw block sums, applies it.
// ---------------------------------------------------------------------------
__global__ __launch_bounds__(SCAN_B)
void scan_apply_kernel(int n) {
    __shared__ int sb[128];
    int tid = threadIdx.x;
    int b = blockIdx.x;
    if (tid < 128) sb[tid] = (tid < b) ? g_bsum[tid] : 0;  // b < NBLK <= 98 < 128
    __syncthreads();
#pragma unroll
    for (int off = 64; off > 0; off >>= 1) {
        if (tid < off) sb[tid] += sb[tid + off];
        __syncthreads();
    }
    int base = sb[0];
    int i = b * SCAN_B + tid;
    if (i < n) {
        int o = g_off[i] + base;
        g_off[i] = o;
        g_cur[i] = o;
    }
}

// ---------------------------------------------------------------------------
// CSR fill: bucket edges by destination; precompute norm = dinv[s]*dinv[d].
// After this kernel g_cur[v] == g_off[v] + deg[v] (the bucket end).
// ---------------------------------------------------------------------------
__global__ __launch_bounds__(256)
void csr_fill_kernel(const int* __restrict__ src, const int* __restrict__ dst,
                     int e) {
    int i = blockIdx.x * blockDim.x + threadIdx.x;
    int base = i * 4;
    if (base + 3 < e) {
        int4 d = *(const int4*)(dst + base);
        int4 s = *(const int4*)(src + base);
        float n0 = __ldg(&g_dinv[s.x]) * __ldg(&g_dinv[d.x]);
        float n1 = __ldg(&g_dinv[s.y]) * __ldg(&g_dinv[d.y]);
        float n2 = __ldg(&g_dinv[s.z]) * __ldg(&g_dinv[d.z]);
        float n3 = __ldg(&g_dinv[s.w]) * __ldg(&g_dinv[d.w]);
        g_csr[atomicAdd(&g_cur[d.x], 1)] = make_int2(s.x, __float_as_int(n0));
        g_csr[atomicAdd(&g_cur[d.y], 1)] = make_int2(s.y, __float_as_int(n1));
        g_csr[atomicAdd(&g_cur[d.z], 1)] = make_int2(s.z, __float_as_int(n2));
        g_csr[atomicAdd(&g_cur[d.w], 1)] = make_int2(s.w, __float_as_int(n3));
    } else {
        for (int k = base; k < e; k++) {
            int ss = src[k], dd = dst[k];
            float nm = __ldg(&g_dinv[ss]) * __ldg(&g_dinv[dd]);
            g_csr[atomicAdd(&g_cur[dd], 1)] = make_int2(ss, __float_as_int(nm));
        }
    }
}

// ---------------------------------------------------------------------------
// GEMM: h = x @ W  (fp32 math, 256x64 tile, 8x8 per thread, fp16 output)
// ---------------------------------------------------------------------------
__global__ __launch_bounds__(256, 2)
void gemm_kernel(const float* __restrict__ x, const float* __restrict__ W,
                 int n) {
    __shared__ float xs[256][33];     // +1 pad vs bank conflicts
    __shared__ float ws[32][OUT_CH];  // k-chunk x all 64 cols

    const int tx  = threadIdx.x;      // 0..7  -> 8 cols each
    const int ty  = threadIdx.y;      // 0..31 -> 8 rows each
    const int tid = ty * 8 + tx;
    const int row0 = blockIdx.x * 256;

    float acc[8][8];
#pragma unroll
    for (int i = 0; i < 8; i++)
#pragma unroll
        for (int j = 0; j < 8; j++) acc[i][j] = 0.0f;

    for (int kc = 0; kc < IN_CH; kc += 32) {
#pragma unroll
        for (int t = 0; t < 8; t++) {
            int li = tid + t * 256;     // 0..2047
            int r  = li >> 3;           // 0..255
            int k4 = li & 7;
            float4 v = make_float4(0.f, 0.f, 0.f, 0.f);
            if (row0 + r < n)
                v = *(const float4*)(x + (size_t)(row0 + r) * IN_CH + kc + k4 * 4);
            xs[r][k4 * 4 + 0] = v.x;
            xs[r][k4 * 4 + 1] = v.y;
            xs[r][k4 * 4 + 2] = v.z;
            xs[r][k4 * 4 + 3] = v.w;
        }
#pragma unroll
        for (int t = 0; t < 2; t++) {
            int li = tid + t * 256;
            int k  = li >> 4;
            int c4 = li & 15;
            *(float4*)&ws[k][c4 * 4] =
                *(const float4*)(W + (size_t)(kc + k) * OUT_CH + c4 * 4);
        }
        __syncthreads();

#pragma unroll
        for (int kk = 0; kk < 32; kk++) {
            float4 b0 = *(float4*)&ws[kk][tx * 8];
            float4 b1 = *(float4*)&ws[kk][tx * 8 + 4];
#pragma unroll
            for (int i = 0; i < 8; i++) {
                float a = xs[ty * 8 + i][kk];
                acc[i][0] += a * b0.x; acc[i][1] += a * b0.y;
                acc[i][2] += a * b0.z; acc[i][3] += a * b0.w;
                acc[i][4] += a * b1.x; acc[i][5] += a * b1.y;
                acc[i][6] += a * b1.z; acc[i][7] += a * b1.w;
            }
        }
        __syncthreads();
    }

    // Epilogue: convert to fp16 and store as one 16B transaction per row-chunk
#pragma unroll
    for (int i = 0; i < 8; i++) {
        int r = row0 + ty * 8 + i;
        if (r < n) {
            __half2 hbuf[4];
            hbuf[0] = __floats2half2_rn(acc[i][0], acc[i][1]);
            hbuf[1] = __floats2half2_rn(acc[i][2], acc[i][3]);
            hbuf[2] = __floats2half2_rn(acc[i][4], acc[i][5]);
            hbuf[3] = __floats2half2_rn(acc[i][6], acc[i][7]);
            __half2* hp = g_hh + (size_t)r * (OUT_CH / 2) + tx * 4;
            *(uint4*)hp = *(const uint4*)hbuf;
        }
    }
}

// ---------------------------------------------------------------------------
// Aggregate: 8 threads per node, each owns 8 channels (one uint4 = 16B/edge).
// CSR carries (src, norm): 2-level load chain csr(coalesced) -> h(gather).
// out[v] = relu( dv^2*h[v] + sum_e norm_e*h[src_e] + b )
// ---------------------------------------------------------------------------
__device__ __forceinline__ void h8_to_f8(uint4 u, float* f) {
    const __half2* hp = (const __half2*)&u;
    float2 f0 = __half22float2(hp[0]);
    float2 f1 = __half22float2(hp[1]);
    float2 f2 = __half22float2(hp[2]);
    float2 f3 = __half22float2(hp[3]);
    f[0] = f0.x; f[1] = f0.y; f[2] = f1.x; f[3] = f1.y;
    f[4] = f2.x; f[5] = f2.y; f[6] = f3.x; f[7] = f3.y;
}

__global__ __launch_bounds__(256)
void aggregate_kernel(const float* __restrict__ b, float* __restrict__ out,
                      int n) {
    int idx = blockIdx.x * blockDim.x + threadIdx.x;
    int v = idx >> 3;
    if (v >= n) return;
    int q = idx & 7;

    const uint4* hh4 = (const uint4*)g_hh;   // 16B granules; node stride 8

    float dv = g_dinv[v];
    float d2 = dv * dv;

    // self-loop contribution: dv^2 * h[v]
    float a[8];
    {
        float f[8];
        h8_to_f8(__ldg(&hh4[(size_t)v * 8 + q]), f);
#pragma unroll
        for (int k = 0; k < 8; k++) a[k] = d2 * f[k];
    }

    int j = g_off[v];
    const int end = g_cur[v];    // == off + deg after csr_fill

    for (; j < end; j += 8) {
        int2  c[8];
        uint4 hv[8];
#pragma unroll
        for (int t = 0; t < 8; t++)
            c[t] = (j + t < end) ? __ldg(&g_csr[j + t]) : make_int2(0, 0);
#pragma unroll
        for (int t = 0; t < 8; t++)
            hv[t] = __ldg(&hh4[(size_t)c[t].x * 8 + q]);
#pragma unroll
        for (int t = 0; t < 8; t++) {
            float nm = __int_as_float(c[t].y);
            float f[8];
            h8_to_f8(hv[t], f);
#pragma unroll
            for (int k = 0; k < 8; k++) a[k] = fmaf(nm, f[k], a[k]);
        }
    }

    // bias + relu; thread q covers channels [q*8, q*8+8)
    const float4* bb = (const float4*)b;
    float4 b0 = bb[q * 2], b1 = bb[q * 2 + 1];
    float4 o0, o1;
    o0.x = fmaxf(a[0] + b0.x, 0.f);
    o0.y = fmaxf(a[1] + b0.y, 0.f);
    o0.z = fmaxf(a[2] + b0.z, 0.f);
    o0.w = fmaxf(a[3] + b0.w, 0.f);
    o1.x = fmaxf(a[4] + b1.x, 0.f);
    o1.y = fmaxf(a[5] + b1.y, 0.f);
    o1.z = fmaxf(a[6] + b1.z, 0.f);
    o1.w = fmaxf(a[7] + b1.w, 0.f);
    float4* op = (float4*)(out + (size_t)v * OUT_CH);
    op[q * 2]     = o0;
    op[q * 2 + 1] = o1;
}

// ---------------------------------------------------------------------------
extern "C" void kernel_launch(void* const* d_in, const int* in_sizes, int n_in,
                              void* d_out, int out_size) {
    const float* x  = (const float*)d_in[0];
    const int*   ei = (const int*)d_in[1];
    const float* W  = (const float*)d_in[2];
    const float* b  = (const float*)d_in[3];
    float*       out = (float*)d_out;

    const int n = in_sizes[0] / IN_CH;   // 100000
    const int e = in_sizes[1] / 2;       // 1600000
    const int* src = ei;                 // edge_index[0]
    const int* dst = ei + e;             // edge_index[1]

    // Lazy one-time setup (first call is the non-captured correctness run)
    static cudaStream_t s2 = nullptr;
    static cudaEvent_t ev_fork = nullptr, ev_join = nullptr;
    static void* deg_ptr = nullptr;
    if (s2 == nullptr) {
        cudaStreamCreateWithFlags(&s2, cudaStreamNonBlocking);
        cudaEventCreateWithFlags(&ev_fork, cudaEventDisableTiming);
        cudaEventCreateWithFlags(&ev_join, cudaEventDisableTiming);
        cudaGetSymbolAddress(&deg_ptr, g_deg);
    }

    // Fork: GEMM on s2 runs concurrently with the degree/CSR chain
    cudaEventRecord(ev_fork, 0);
    cudaStreamWaitEvent(s2, ev_fork, 0);

    dim3 tb(8, 32);
    gemm_kernel<<<(n + 255) / 256, tb, 0, s2>>>(x, W, n);

    cudaMemsetAsync(deg_ptr, 0, (size_t)n * sizeof(int), 0);
    deg_count_kernel<<<(e / 4 + 255) / 256, 256>>>(dst, e);

    int nblk = (n + SCAN_B - 1) / SCAN_B;
    scan_block_kernel<<<nblk, SCAN_B>>>(n);
    scan_apply_kernel<<<nblk, SCAN_B>>>(n);

    csr_fill_kernel<<<(e / 4 + 255) / 256, 256>>>(src, dst, e);

    // Join: aggregate needs both h (s2) and the CSR (stream 0)
    cudaEventRecord(ev_join, s2);
    cudaStreamWaitEvent(0, ev_join, 0);

    long ag_threads = (long)n * 8;
    aggregate_kernel<<<(int)((ag_threads + 255) / 256), 256>>>(b, out, n);
}